// round 6
// baseline (speedup 1.0000x reference)
#include <cuda_runtime.h>
#include <cuda_bf16.h>

#define SIDE 9
#define STATE 81
#define NA 5
#define ROWLEN (STATE * NA)   // 405
#define H 32
#define RPB 32                // rows per block
#define GROUP 8               // rows staged per group
#define THREADS 256

// ---------------------------------------------------------------------------
// Packed f32x2 helpers (sm_103a FFMA2)
// ---------------------------------------------------------------------------
__device__ __forceinline__ unsigned long long pack2(float x) {
    unsigned long long r;
    asm("mov.b64 %0, {%1, %1};" : "=l"(r) : "f"(x));
    return r;
}
__device__ __forceinline__ void ffma2(unsigned long long& d,
                                      unsigned long long a,
                                      unsigned long long b) {
    asm("fma.rn.f32x2 %0, %1, %2, %0;" : "+l"(d) : "l"(a), "l"(b));
}
__device__ __forceinline__ void unpack2(unsigned long long p, float& lo, float& hi) {
    asm("mov.b64 {%0, %1}, %2;" : "=f"(lo), "=f"(hi) : "l"(p));
}

__global__ __launch_bounds__(THREADS) void vpn_fused(
    const float* __restrict__ obs,          // (B, 3*STATE)
    const float* __restrict__ acr_g,        // (B, STATE*NA)
    const float* __restrict__ W1,           // (STATE, 32)
    const float* __restrict__ W2,           // (32, 32)
    const float* __restrict__ W3,           // (32, 1)
    const float* __restrict__ b3,           // (1,)
    float* __restrict__ out,                // [sym(B), imm(B), ret(B), nsc(B*81)]
    int B)
{
    __shared__ float s_ac[GROUP * ROWLEN];    // 12.96 KB (one 8-row group)
    __shared__ float s_nsc[RPB * STATE];      // 10.37 KB
    __shared__ float s_h1[RPB * 36];          //  4.6 KB (padded stride 36)
    __shared__ float s_imm[RPB];
    __shared__ float sW1[STATE * H];          // 10.37 KB
    __shared__ float sW2[H * H];              //  4 KB
    __shared__ float sW3[H];
    __shared__ float sb3;

    const int tid  = threadIdx.x;
    const int wid  = tid >> 5;
    const int lane = tid & 31;
    const long long blockRow0 = (long long)blockIdx.x * RPB;

    // Stage weights (consumed after the first __syncthreads in the group loop).
    for (int i = tid; i < STATE * H; i += THREADS) sW1[i] = W1[i];
    for (int i = tid; i < H * H; i += THREADS)     sW2[i] = W2[i];
    if (tid < H)  sW3[tid] = W3[tid];
    if (tid == 0) sb3 = b3[0];

    // ---------------- Phase A: scatter-gather + reward, 4 groups of 8 rows --
    #pragma unroll
    for (int q = 0; q < RPB / GROUP; q++) {
        const long long gRow0 = blockRow0 + q * GROUP;

        // Block-wide stage of 8 contiguous rows (3240 floats) via float4.
        if (gRow0 + GROUP <= B) {
            const float4* __restrict__ src =
                reinterpret_cast<const float4*>(acr_g + gRow0 * ROWLEN);
            float4* __restrict__ dst = reinterpret_cast<float4*>(s_ac);
            #pragma unroll
            for (int i = tid; i < GROUP * ROWLEN / 4; i += THREADS)
                dst[i] = __ldg(&src[i]);
        } else {
            for (int i = tid; i < GROUP * ROWLEN; i += THREADS) {
                const long long gi = gRow0 * ROWLEN + i;
                if (gi < (long long)B * ROWLEN) s_ac[i] = acr_g[gi];
            }
        }
        __syncthreads();

        // Warp w gathers row gRow0 + w.
        const long long row = gRow0 + wid;
        if (row < B) {
            const float* __restrict__ sp = s_ac + wid * ROWLEN;
            const float* __restrict__ dem = obs + row * (3 * STATE) + 2 * STATE;
            float* __restrict__ nout = out + 3LL * B + row * STATE;
            float* __restrict__ nrow = s_nsc + (q * GROUP + wid) * STATE;

            float imm = 0.0f;
            #pragma unroll
            for (int k = 0; k < 3; k++) {
                const int c = lane + 32 * k;
                if (c < STATE) {
                    const int rr  = c / SIDE;
                    const int col = c - rr * SIDE;
                    float v = sp[c * NA + 0];
                    if (rr == 0)        v += sp[c * NA + 1];
                    if (rr < SIDE - 1)  v += sp[(c + SIDE) * NA + 1];
                    if (rr == SIDE - 1) v += sp[c * NA + 2];
                    if (rr > 0)         v += sp[(c - SIDE) * NA + 2];
                    if (col == 0)       v += sp[c * NA + 3];
                    if (col < SIDE - 1) v += sp[(c + 1) * NA + 3];
                    if (col == SIDE-1)  v += sp[c * NA + 4];
                    if (col > 0)        v += sp[(c - 1) * NA + 4];

                    nrow[c] = v;                      // smem (conflict-free)
                    nout[c] = v;                      // gmem (coalesced)
                    imm += fminf(v, __ldg(&dem[c]));
                }
            }
            #pragma unroll
            for (int o = 16; o; o >>= 1)
                imm += __shfl_xor_sync(0xffffffffu, imm, o);
            if (lane == 0) {
                out[(long long)B + row] = imm;
                s_imm[q * GROUP + wid] = imm;
            }
        }
        __syncthreads();   // all reads of s_ac done before restage
    }

    // ---------------- Phase B: MLP, thread = (1 row x 4 cols) ---------------
    const int r = tid >> 3;        // row within block, warp owns rows 4w..4w+3
    const int g = tid & 7;         // column group: cols 4g..4g+3
    const long long b = blockRow0 + r;

    const float* __restrict__ myn = s_nsc + r * STATE;

    unsigned long long h01 = 0ULL, h23 = 0ULL;
    #pragma unroll 27
    for (int d = 0; d < STATE; d++) {
        const unsigned long long v = pack2(myn[d]);   // broadcast LDS.32
        const ulonglong2 w =
            *reinterpret_cast<const ulonglong2*>(&sW1[d * H + 4 * g]);
        ffma2(h01, v, w.x);
        ffma2(h23, v, w.y);
    }

    // ReLU + publish h1 (4 floats) to smem for the layer-2 column exchange.
    {
        float a0, a1, a2, a3;
        unpack2(h01, a0, a1);
        unpack2(h23, a2, a3);
        float4 hv = make_float4(fmaxf(a0, 0.f), fmaxf(a1, 0.f),
                                fmaxf(a2, 0.f), fmaxf(a3, 0.f));
        *reinterpret_cast<float4*>(&s_h1[r * 36 + 4 * g]) = hv;
    }
    __syncwarp();   // rows 4w..4w+3 are produced and consumed by warp w only

    unsigned long long z01 = 0ULL, z23 = 0ULL;
    #pragma unroll
    for (int j = 0; j < H; j++) {
        const unsigned long long hv = pack2(s_h1[r * 36 + j]);
        const ulonglong2 w =
            *reinterpret_cast<const ulonglong2*>(&sW2[j * H + 4 * g]);
        ffma2(z01, hv, w.x);
        ffma2(z23, hv, w.y);
    }

    // Layer 3 partial: relu(z) . W3[4g..4g+3], then reduce over the 8 column
    // groups of this row (lanes differing only in g -> xor offsets 1,2,4).
    float part;
    {
        float z0, z1, z2, z3;
        unpack2(z01, z0, z1);
        unpack2(z23, z2, z3);
        const float4 w3 = *reinterpret_cast<const float4*>(&sW3[4 * g]);
        part  = fmaxf(z0, 0.f) * w3.x;
        part += fmaxf(z1, 0.f) * w3.y;
        part += fmaxf(z2, 0.f) * w3.z;
        part += fmaxf(z3, 0.f) * w3.w;
    }
    part += __shfl_xor_sync(0xffffffffu, part, 1);
    part += __shfl_xor_sync(0xffffffffu, part, 2);
    part += __shfl_xor_sync(0xffffffffu, part, 4);

    if (g == 0 && b < B) {
        const float ret = part + sb3;
        const float imm = s_imm[r];
        out[b]                      = imm + ret;  // symbolic_val
        out[2LL * (long long)B + b] = ret;        // next_return
    }
}

extern "C" void kernel_launch(void* const* d_in, const int* in_sizes, int n_in,
                              void* d_out, int out_size) {
    const float* obs = (const float*)d_in[0];
    const float* action_count = (const float*)d_in[1];
    const float* W1 = (const float*)d_in[2];
    const float* W2 = (const float*)d_in[3];
    const float* W3 = (const float*)d_in[4];
    const float* b3 = (const float*)d_in[5];
    float* out = (float*)d_out;

    const int B = in_sizes[0] / (3 * STATE);
    const int blocks = (B + RPB - 1) / RPB;
    vpn_fused<<<blocks, THREADS>>>(obs, action_count, W1, W2, W3, b3, out, B);
}

// round 7
// speedup vs baseline: 1.5260x; 1.5260x over previous
#include <cuda_runtime.h>
#include <cuda_bf16.h>

#define SIDE 9
#define STATE 81
#define NA 5
#define H 32
#define WARPS_K1 8
#define MAX_B 131072

// nsc transposed scratch: [d][b], d-stride = B (<= MAX_B)
__device__ float g_nscT[(size_t)STATE * MAX_B];

// ---------------------------------------------------------------------------
// K1: warp-per-row scatter + reward (round-2 proven structure) + transposed
// scratch write for K2's coalesced consumption.
// ---------------------------------------------------------------------------
__global__ __launch_bounds__(32 * WARPS_K1) void k1_nsc_reward(
    const float* __restrict__ obs,          // (B, 3*STATE)
    const float* __restrict__ acr_g,        // (B, STATE*NA)
    float* __restrict__ out,                // [sym(B), imm(B), ret(B), nsc(B*81)]
    int B)
{
    __shared__ float s_ac[WARPS_K1][416];
    __shared__ float s_nsc[WARPS_K1 * STATE];

    const int tid  = threadIdx.x;
    const int wid  = tid >> 5;
    const int lane = tid & 31;
    const long long row0 = (long long)blockIdx.x * WARPS_K1;
    const long long row  = row0 + wid;

    if (row < B) {
        const float* __restrict__ acr = acr_g + row * (STATE * NA);
        float* __restrict__ sp = s_ac[wid];
        #pragma unroll
        for (int k = 0; k < 13; k++) {
            const int i = lane + 32 * k;
            if (i < STATE * NA) sp[i] = __ldg(&acr[i]);
        }
        __syncwarp();

        const float* __restrict__ dem = obs + row * (3 * STATE) + 2 * STATE;
        float* __restrict__ nout = out + 3LL * B + row * STATE;
        float* __restrict__ nrow = s_nsc + wid * STATE;

        float imm = 0.0f;
        #pragma unroll
        for (int k = 0; k < 3; k++) {
            const int c = lane + 32 * k;
            if (c < STATE) {
                const int r   = c / SIDE;
                const int col = c - r * SIDE;
                float v = sp[c * NA + 0];
                if (r == 0)        v += sp[c * NA + 1];
                if (r < SIDE - 1)  v += sp[(c + SIDE) * NA + 1];
                if (r == SIDE - 1) v += sp[c * NA + 2];
                if (r > 0)         v += sp[(c - SIDE) * NA + 2];
                if (col == 0)      v += sp[c * NA + 3];
                if (col < SIDE - 1)v += sp[(c + 1) * NA + 3];
                if (col == SIDE-1) v += sp[c * NA + 4];
                if (col > 0)       v += sp[(c - 1) * NA + 4];

                nout[c] = v;                      // gmem, coalesced
                nrow[c] = v;                      // smem, conflict-free
                imm += fminf(v, __ldg(&dem[c]));
            }
        }

        #pragma unroll
        for (int o = 16; o; o >>= 1) imm += __shfl_xor_sync(0xffffffffu, imm, o);
        if (lane == 0) out[(long long)B + row] = imm;
    }
    __syncthreads();

    // Transposed write: g_nscT[d*B + row0 + j] = s_nsc[j*81 + d].
    // Warp covers 4 d-values x 8 rows -> 4x32B coalesced segments.
    for (int i = tid; i < STATE * WARPS_K1; i += 32 * WARPS_K1) {
        const int d = i >> 3;
        const int j = i & 7;
        if (row0 + j < B)
            g_nscT[(long long)d * B + row0 + j] = s_nsc[j * STATE + d];
    }
}

// ---------------------------------------------------------------------------
// Packed f32x2 helpers (sm_103a FFMA2)
// ---------------------------------------------------------------------------
__device__ __forceinline__ unsigned long long pack2(float x) {
    unsigned long long r;
    asm("mov.b64 %0, {%1, %1};" : "=l"(r) : "f"(x));
    return r;
}
__device__ __forceinline__ void ffma2(unsigned long long& d,
                                      unsigned long long a,
                                      unsigned long long b) {
    asm("fma.rn.f32x2 %0, %1, %2, %0;" : "+l"(d) : "l"(a), "l"(b));
}
__device__ __forceinline__ void unpack2(unsigned long long p, float& lo, float& hi) {
    asm("mov.b64 {%0, %1}, %2;" : "=f"(lo), "=f"(hi) : "l"(p));
}

// ---------------------------------------------------------------------------
// K2: thread-per-row MLP streaming nsc from the transposed scratch.
// Every nsc load is a fully-coalesced LDG.32 (1 wavefront/warp/d).
// Weights in 14.6KB smem -> ~32 warps/SM.
// ---------------------------------------------------------------------------
__global__ __launch_bounds__(256) void k2_mlp(
    const float* __restrict__ W1,
    const float* __restrict__ W2,
    const float* __restrict__ W3,
    const float* __restrict__ b3,
    float* __restrict__ out,
    int B)
{
    __shared__ float sW1[STATE * H];
    __shared__ float sW2[H * H];
    __shared__ float sW3[H];
    __shared__ float sb3;

    for (int i = threadIdx.x; i < STATE * H; i += blockDim.x) sW1[i] = W1[i];
    for (int i = threadIdx.x; i < H * H; i += blockDim.x)     sW2[i] = W2[i];
    if (threadIdx.x < H)  sW3[threadIdx.x] = W3[threadIdx.x];
    if (threadIdx.x == 0) sb3 = b3[0];
    __syncthreads();

    const long long b = (long long)blockIdx.x * blockDim.x + threadIdx.x;
    if (b >= B) return;

    unsigned long long h1p[H / 2];
    #pragma unroll
    for (int j = 0; j < H / 2; j++) h1p[j] = 0ULL;

    // Layer 1: stream v_d from transposed scratch (coalesced LDG.32).
    #pragma unroll 9
    for (int d = 0; d < STATE; d++) {
        const unsigned long long vd = pack2(__ldg(&g_nscT[(long long)d * B + b]));
        const ulonglong2* __restrict__ w1p =
            reinterpret_cast<const ulonglong2*>(&sW1[d * H]);
        #pragma unroll
        for (int q = 0; q < H / 4; q++) {
            ulonglong2 w = w1p[q];
            ffma2(h1p[q * 2 + 0], vd, w.x);
            ffma2(h1p[q * 2 + 1], vd, w.y);
        }
    }

    float h1[H];
    #pragma unroll
    for (int j = 0; j < H / 2; j++) {
        float lo, hi;
        unpack2(h1p[j], lo, hi);
        h1[2 * j + 0] = fmaxf(lo, 0.0f);
        h1[2 * j + 1] = fmaxf(hi, 0.0f);
    }

    unsigned long long h2p[H / 2];
    #pragma unroll
    for (int j = 0; j < H / 2; j++) h2p[j] = 0ULL;
    #pragma unroll
    for (int i = 0; i < H; i++) {
        const unsigned long long vi = pack2(h1[i]);
        const ulonglong2* __restrict__ w2p =
            reinterpret_cast<const ulonglong2*>(&sW2[i * H]);
        #pragma unroll
        for (int q = 0; q < H / 4; q++) {
            ulonglong2 w = w2p[q];
            ffma2(h2p[q * 2 + 0], vi, w.x);
            ffma2(h2p[q * 2 + 1], vi, w.y);
        }
    }

    float ret = sb3;
    #pragma unroll
    for (int j = 0; j < H / 2; j++) {
        float lo, hi;
        unpack2(h2p[j], lo, hi);
        ret = fmaf(fmaxf(lo, 0.0f), sW3[2 * j + 0], ret);
        ret = fmaf(fmaxf(hi, 0.0f), sW3[2 * j + 1], ret);
    }

    const float imm = out[(long long)B + b];   // coalesced
    out[b]                      = imm + ret;   // symbolic_val
    out[2LL * (long long)B + b] = ret;         // next_return
}

extern "C" void kernel_launch(void* const* d_in, const int* in_sizes, int n_in,
                              void* d_out, int out_size) {
    const float* obs = (const float*)d_in[0];
    const float* action_count = (const float*)d_in[1];
    const float* W1 = (const float*)d_in[2];
    const float* W2 = (const float*)d_in[3];
    const float* W3 = (const float*)d_in[4];
    const float* b3 = (const float*)d_in[5];
    float* out = (float*)d_out;

    const int B = in_sizes[0] / (3 * STATE);

    const int blocks1 = (B + WARPS_K1 - 1) / WARPS_K1;
    k1_nsc_reward<<<blocks1, 32 * WARPS_K1>>>(obs, action_count, out, B);

    const int threads2 = 256;
    const int blocks2 = (B + threads2 - 1) / threads2;
    k2_mlp<<<blocks2, threads2>>>(W1, W2, W3, b3, out, B);
}